// round 12
// baseline (speedup 1.0000x reference)
#include <cuda_runtime.h>
#include <cuda_fp16.h>
#include <cstdint>

#define T_TOK 16384
#define DIM   1024
#define HID   4096

#define BM 128
#define BN 256
#define BK 64                       // 64 halves = 128B of K per row
#define NT 256                      // 8 warps: 2x4 grid, warp tile 64x64
#define KT1 (DIM / BK)              // 16 k-tiles (gemm1)
#define KT2 (HID / BK)              // 64 k-tiles (gemm2)

#define A_TILE 16384                // 128 rows x 128B
#define B_TILE 32768                // 256 rows x 128B
#define PAIR_A (2 * A_TILE)         // 32768
#define PAIR_B (2 * B_TILE)         // 65536
#define PAIR_BYTES (PAIR_A + PAIR_B)   // 98304
#define SMEM_BYTES (2 * PAIR_BYTES)    // 196608

// ---------------- scratch: pre-swizzled tiled fp16 operands ----------------
__device__ __align__(256) unsigned char g_Xh[(size_t)T_TOK * DIM * 2];   // 32MB
__device__ __align__(256) unsigned char g_Hh[(size_t)T_TOK * HID * 2];   // 128MB
__device__ __align__(256) unsigned char g_w1h[(size_t)HID * DIM * 2];    // 8MB
__device__ __align__(256) unsigned char g_w2h[(size_t)DIM * HID * 2];    // 8MB
__device__ int g_perm[T_TOK];
__device__ int g_rowd[T_TOK];
__device__ int g_off[4], g_cur[4];

// ---------------- helpers ----------------
__device__ __forceinline__ uint32_t smem_u32(const void* p) {
    return (uint32_t)__cvta_generic_to_shared(p);
}
__device__ __forceinline__ uint32_t swz(uint32_t r, uint32_t c8) {
    return r * 128u + (((c8) ^ (r & 7u)) << 4);
}
__device__ __forceinline__ float gelu_exact(float v) {
    return 0.5f * v * (1.0f + erff(v * 0.70710678118654752f));
}

#define MBAR_INIT(a, n) \
    asm volatile("mbarrier.init.shared.b64 [%0], %1;" :: "r"(a), "r"((uint32_t)(n)) : "memory")
#define MBAR_EXPECT_TX(a, b) \
    asm volatile("mbarrier.arrive.expect_tx.shared.b64 _, [%0], %1;" :: "r"(a), "r"((uint32_t)(b)) : "memory")
#define MBAR_WAIT(a, par) do {                                              \
    asm volatile("{\n\t.reg .pred P1;\n\t"                                  \
        "WL_%=:\n\t"                                                        \
        "mbarrier.try_wait.parity.acquire.cta.shared::cta.b64 P1, [%0], %1, 0x989680;\n\t" \
        "@P1 bra.uni WD_%=;\n\t"                                            \
        "bra.uni WL_%=;\n\t"                                                \
        "WD_%=:\n\t}"                                                       \
        :: "r"(a), "r"((uint32_t)(par)) : "memory");                        \
} while (0)
#define BULK_G2S(dst, src, nbytes, mbar) \
    asm volatile("cp.async.bulk.shared::cluster.global.mbarrier::complete_tx::bytes [%0], [%1], %2, [%3];" \
        :: "r"(dst), "l"(src), "r"((uint32_t)(nbytes)), "r"(mbar) : "memory")

#define LDSM_X4(r0, r1, r2, r3, addr) \
    asm volatile("ldmatrix.sync.aligned.m8n8.x4.shared.b16 {%0,%1,%2,%3}, [%4];" \
        : "=r"(r0), "=r"(r1), "=r"(r2), "=r"(r3) : "r"(addr))

__device__ __forceinline__ void mma16(float* c, const uint32_t* a, uint32_t b0, uint32_t b1) {
    asm volatile(
        "mma.sync.aligned.m16n8k16.row.col.f32.f16.f16.f32 "
        "{%0,%1,%2,%3}, {%4,%5,%6,%7}, {%8,%9}, {%0,%1,%2,%3};\n"
        : "+f"(c[0]), "+f"(c[1]), "+f"(c[2]), "+f"(c[3])
        : "r"(a[0]), "r"(a[1]), "r"(a[2]), "r"(a[3]), "r"(b0), "r"(b1));
}

// ---------------- launch 0: histogram + offsets (one CTA) ----------------
__global__ void k_hist(const int* __restrict__ mask) {
    const int tid = threadIdx.x;          // 1024 threads
    int c0 = 0, c1 = 0, c2 = 0, c3 = 0;
    const int4* m4 = (const int4*)mask;
    for (int i = tid; i < T_TOK / 4; i += 1024) {
        const int4 e = m4[i];
        c0 += (e.x == 0) + (e.y == 0) + (e.z == 0) + (e.w == 0);
        c1 += (e.x == 1) + (e.y == 1) + (e.z == 1) + (e.w == 1);
        c2 += (e.x == 2) + (e.y == 2) + (e.z == 2) + (e.w == 2);
        c3 += (e.x == 3) + (e.y == 3) + (e.z == 3) + (e.w == 3);
    }
#pragma unroll
    for (int o = 16; o; o >>= 1) {
        c0 += __shfl_xor_sync(~0u, c0, o);
        c1 += __shfl_xor_sync(~0u, c1, o);
        c2 += __shfl_xor_sync(~0u, c2, o);
        c3 += __shfl_xor_sync(~0u, c3, o);
    }
    __shared__ int sh[4];
    if (tid < 4) sh[tid] = 0;
    __syncthreads();
    if ((tid & 31) == 0) {
        atomicAdd(&sh[0], c0); atomicAdd(&sh[1], c1);
        atomicAdd(&sh[2], c2); atomicAdd(&sh[3], c3);
    }
    __syncthreads();
    if (tid == 0) {
        int s = 0;
        for (int e = 0; e < 4; e++) { g_off[e] = s; s += sh[e]; g_cur[e] = 0; }
    }
}

// ---------------- launch 1: scatter rank + gather + K-mask + fp16 + tile/swizzle ----------------
#define TPB_TOKENS 64
__global__ void k_scatter_prep(const float* __restrict__ x, const int* __restrict__ mask) {
    __shared__ int sp[TPB_TOKENS], sd[TPB_TOKENS];
    const int tid  = threadIdx.x;         // 256 threads
    const int base = blockIdx.x * TPB_TOKENS;
    if (tid < TPB_TOKENS) {
        const int t = base + tid;
        const int e = mask[t];
        const int p = g_off[e] + atomicAdd(&g_cur[e], 1);
        g_perm[p] = t;
        g_rowd[p] = 128 << e;
        sp[tid] = p;
        sd[tid] = 128 << e;
    }
    __syncthreads();
    const int sub = tid >> 7;             // 0..1 : which of 2 tokens this pass
    const int cc  = tid & 127;            // 16B-chunk index within the 2KB row
    const int tkt = cc >> 3;              // k-tile 0..15
    const int c8  = cc & 7;               // chunk within 128B row
    for (int tk = 0; tk < TPB_TOKENS; tk += 2) {
        const int tok = base + tk + sub;
        const int p = sp[tk + sub], d = sd[tk + sub];
        const int i = p >> 7, r = p & 127;
        uint4 v = make_uint4(0u, 0u, 0u, 0u);
        if (cc * 8 < d) {                 // d multiple of 128 -> chunk uniform
            const float4 f0 = ((const float4*)(x + (size_t)tok * DIM + cc * 8))[0];
            const float4 f1 = ((const float4*)(x + (size_t)tok * DIM + cc * 8))[1];
            __half2 h0 = __floats2half2_rn(f0.x, f0.y);
            __half2 h1 = __floats2half2_rn(f0.z, f0.w);
            __half2 h2 = __floats2half2_rn(f1.x, f1.y);
            __half2 h3 = __floats2half2_rn(f1.z, f1.w);
            v.x = *(uint32_t*)&h0; v.y = *(uint32_t*)&h1;
            v.z = *(uint32_t*)&h2; v.w = *(uint32_t*)&h3;
        }
        *(uint4*)(g_Xh + (size_t)(i * KT1 + tkt) * A_TILE + swz(r, c8)) = v;
    }
}

// ---------------- launch 2: weight conversion + tile/swizzle ----------------
__global__ void k_cvt(const float* __restrict__ w1, const float* __restrict__ w2) {
    const int q = blockIdx.x * blockDim.x + threadIdx.x;   // one 16B half-chunk each
    const int n1 = (HID * DIM * 2) / 16;                    // 524288 chunks for w1
    const float* src;
    unsigned char* dst;
    if (q < n1) {
        const int tile = q >> 11;          // 2048 chunks per 32KB tile
        const int w = q & 2047;
        const int r = w >> 3, c8 = w & 7;  // row 0..255, chunk 0..7
        const int j = tile >> 4, t = tile & (KT1 - 1);      // j 0..15, t 0..15
        src = w1 + (size_t)(j * 256 + r) * DIM + t * 64 + c8 * 8;
        dst = g_w1h + (size_t)tile * B_TILE + swz(r, c8);
    } else {
        const int p = q - n1;
        const int tile = p >> 11;
        const int w = p & 2047;
        const int r = w >> 3, c8 = w & 7;
        const int j = tile >> 6, t = tile & (KT2 - 1);      // j 0..3, t 0..63
        src = w2 + (size_t)(j * 256 + r) * HID + t * 64 + c8 * 8;
        dst = g_w2h + (size_t)tile * B_TILE + swz(r, c8);
    }
    const float4 f0 = ((const float4*)src)[0];
    const float4 f1 = ((const float4*)src)[1];
    __half2 h0 = __floats2half2_rn(f0.x, f0.y);
    __half2 h1 = __floats2half2_rn(f0.z, f0.w);
    __half2 h2 = __floats2half2_rn(f1.x, f1.y);
    __half2 h3 = __floats2half2_rn(f1.z, f1.w);
    uint4 v;
    v.x = *(uint32_t*)&h0; v.y = *(uint32_t*)&h1;
    v.z = *(uint32_t*)&h2; v.w = *(uint32_t*)&h3;
    *(uint4*)dst = v;
}

// ---------------- per-stage compute: warp tile 64x64, xor-swizzled LDSM ----------------
__device__ __forceinline__ void tile_compute(uint32_t sA, uint32_t sB,
                                             const uint32_t (&arow)[4], const uint32_t (&axr)[4],
                                             const uint32_t (&brow)[4], const uint32_t (&bxr)[4],
                                             uint32_t abit, uint32_t cbit,
                                             float (&acc)[4][8][4]) {
#pragma unroll
    for (uint32_t kc = 0; kc < 4; kc++) {
        uint32_t a[4][4], b[4][4];
        const uint32_t ca = kc * 2 + cbit;   // A chunk index before swizzle
        const uint32_t cb = kc * 2 + abit;   // B chunk index before swizzle
#pragma unroll
        for (int mi = 0; mi < 4; mi++) {
            LDSM_X4(a[mi][0], a[mi][1], a[mi][2], a[mi][3],
                    sA + arow[mi] + ((ca ^ axr[mi]) << 4));
        }
#pragma unroll
        for (int g = 0; g < 4; g++) {
            LDSM_X4(b[g][0], b[g][1], b[g][2], b[g][3],
                    sB + brow[g] + ((cb ^ bxr[g]) << 4));
        }
#pragma unroll
        for (int mi = 0; mi < 4; mi++)
#pragma unroll
            for (int g = 0; g < 4; g++) {
                mma16(acc[mi][2 * g],     a[mi], b[g][0], b[g][1]);
                mma16(acc[mi][2 * g + 1], a[mi], b[g][2], b[g][3]);
            }
    }
}

// ---------------- GEMM mainloop: bulk-copy pairs, 2 buffers, 2 mbarriers ----------------
__device__ __forceinline__ void gemm_main(const unsigned char* __restrict__ At,
                                          const unsigned char* __restrict__ Bt,
                                          int nk, uint32_t sb, uint32_t mb0, uint32_t mb1,
                                          float (&acc)[4][8][4], int tid,
                                          const uint32_t (&arow)[4], const uint32_t (&axr)[4],
                                          const uint32_t (&brow)[4], const uint32_t (&bxr)[4],
                                          uint32_t abit, uint32_t cbit) {
    const int npair = nk >> 1;               // nk even: {2,4,8,16,64}
    if (tid == 0) {
        MBAR_EXPECT_TX(mb0, PAIR_BYTES);
        BULK_G2S(sb, At, PAIR_A, mb0);
        BULK_G2S(sb + PAIR_A, Bt, PAIR_B, mb0);
        if (npair > 1) {
            MBAR_EXPECT_TX(mb1, PAIR_BYTES);
            BULK_G2S(sb + PAIR_BYTES, At + PAIR_A, PAIR_A, mb1);
            BULK_G2S(sb + PAIR_BYTES + PAIR_A, Bt + PAIR_B, PAIR_B, mb1);
        }
    }
    for (int ip = 0; ip < npair; ip++) {
        MBAR_WAIT((ip & 1) ? mb1 : mb0, (ip >> 1) & 1);
        const uint32_t st = sb + (ip & 1) * PAIR_BYTES;
        tile_compute(st, st + PAIR_A, arow, axr, brow, bxr, abit, cbit, acc);
        tile_compute(st + A_TILE, st + PAIR_A + B_TILE, arow, axr, brow, bxr, abit, cbit, acc);
        __syncthreads();                      // buffer (ip&1) free on all warps
        const int np = ip + 2;
        if (np < npair && tid == 0) {
            const uint32_t mb = (ip & 1) ? mb1 : mb0;
            MBAR_EXPECT_TX(mb, PAIR_BYTES);
            BULK_G2S(st, At + (size_t)np * PAIR_A, PAIR_A, mb);
            BULK_G2S(st + PAIR_A, Bt + (size_t)np * PAIR_B, PAIR_B, mb);
        }
    }
}

// ---------------- launch 3 — GEMM1: H = gelu(Xh @ W1h^T + b1) ----------------
__global__ void __launch_bounds__(NT, 1)
k_gemm1(const float* __restrict__ b1) {
    extern __shared__ __align__(1024) char smdyn[];
    __shared__ __align__(8) uint64_t s_mbar[2];
    const uint32_t sb  = smem_u32(smdyn);
    const uint32_t mb0 = smem_u32(&s_mbar[0]);
    const uint32_t mb1 = smem_u32(&s_mbar[1]);

    const int n0   = blockIdx.x * BN;
    const int row0 = blockIdx.y * BM;
    const int tid  = threadIdx.x;
    const int lane = tid & 31, wid = tid >> 5;
    const int wm = wid >> 2, wn = wid & 3;

    if (tid == 0) { MBAR_INIT(mb0, 1); MBAR_INIT(mb1, 1); }
    __syncthreads();

    const uint32_t lr   = lane & 7;
    const uint32_t abit = (lane >> 3) & 1;
    const uint32_t cbit = (lane >> 4) & 1;
    uint32_t arow[4], axr[4], brow[4], bxr[4];
#pragma unroll
    for (int mi = 0; mi < 4; mi++) {
        const uint32_t r = wm * 64 + mi * 16 + lr + abit * 8;
        arow[mi] = r * 128u; axr[mi] = r & 7u;
    }
#pragma unroll
    for (int g = 0; g < 4; g++) {
        const uint32_t r = wn * 64 + g * 16 + lr + cbit * 8;
        brow[g] = r * 128u; bxr[g] = r & 7u;
    }

    float acc[4][8][4];
#pragma unroll
    for (int mi = 0; mi < 4; mi++)
#pragma unroll
        for (int ni = 0; ni < 8; ni++)
#pragma unroll
            for (int r = 0; r < 4; r++) acc[mi][ni][r] = 0.0f;

    const int nk = g_rowd[row0 + BM - 1] / BK;   // sorted: last row has max d; >= 2

    gemm_main(g_Xh + (size_t)blockIdx.y * KT1 * A_TILE,
              g_w1h + (size_t)blockIdx.x * KT1 * B_TILE,
              nk, sb, mb0, mb1, acc, tid, arow, axr, brow, bxr, abit, cbit);

    // epilogue: bias + exact gelu -> fp16 into g_Hh (gemm2 A-tile layout, swizzled)
    const int ti = blockIdx.y;                    // row-tile
#pragma unroll
    for (int mi = 0; mi < 4; mi++) {
        const int rA = wm * 64 + mi * 16 + (lane >> 2);
#pragma unroll
        for (int hh = 0; hh < 2; hh++) {
            const int r = rA + hh * 8;            // row within tile (0..127)
#pragma unroll
            for (int ni = 0; ni < 8; ni++) {
                const int t = (n0 >> 6) + wn;     // gemm2 k-tile index
                const int colg = n0 + wn * 64 + ni * 8 + 2 * (lane & 3);
                const float2 bb = *(const float2*)(b1 + colg);
                float v0 = gelu_exact(acc[mi][ni][hh * 2 + 0] + bb.x);
                float v1 = gelu_exact(acc[mi][ni][hh * 2 + 1] + bb.y);
                __half2 hv = __floats2half2_rn(v0, v1);
                unsigned char* dp = g_Hh + (size_t)(ti * KT2 + t) * A_TILE
                                  + r * 128 + (((uint32_t)ni ^ (r & 7)) << 4)
                                  + ((lane & 3) << 2);
                *(uint32_t*)dp = *(uint32_t*)&hv;
            }
        }
    }
}

// ---------------- launch 4 — GEMM2: Y = mask_out(H @ W2h^T + b2), scattered ----------------
__global__ void __launch_bounds__(NT, 1)
k_gemm2(const float* __restrict__ b2, float* __restrict__ out) {
    extern __shared__ __align__(1024) char smdyn[];
    __shared__ __align__(8) uint64_t s_mbar[2];
    const uint32_t sb  = smem_u32(smdyn);
    const uint32_t mb0 = smem_u32(&s_mbar[0]);
    const uint32_t mb1 = smem_u32(&s_mbar[1]);

    const int n0   = blockIdx.x * BN;
    const int row0 = blockIdx.y * BM;
    const int tid  = threadIdx.x;
    const int dmax = g_rowd[row0 + BM - 1];

    if (n0 >= dmax) {   // whole tile masked -> zero-fill (block-uniform)
        const int row = tid >> 1, half = tid & 1;
        const int tok = g_perm[row0 + row];
        float4* op = (float4*)(out + (size_t)tok * DIM + n0 + half * 128);
        const float4 z = make_float4(0.f, 0.f, 0.f, 0.f);
#pragma unroll
        for (int j = 0; j < 32; j++) op[j] = z;
        return;
    }

    const int lane = tid & 31, wid = tid >> 5;
    const int wm = wid >> 2, wn = wid & 3;

    if (tid == 0) { MBAR_INIT(mb0, 1); MBAR_INIT(mb1, 1); }
    __syncthreads();

    const uint32_t lr   = lane & 7;
    const uint32_t abit = (lane >> 3) & 1;
    const uint32_t cbit = (lane >> 4) & 1;
    uint32_t arow[4], axr[4], brow[4], bxr[4];
#pragma unroll
    for (int mi = 0; mi < 4; mi++) {
        const uint32_t r = wm * 64 + mi * 16 + lr + abit * 8;
        arow[mi] = r * 128u; axr[mi] = r & 7u;
    }
#pragma unroll
    for (int g = 0; g < 4; g++) {
        const uint32_t r = wn * 64 + g * 16 + lr + cbit * 8;
        brow[g] = r * 128u; bxr[g] = r & 7u;
    }

    float acc[4][8][4];
#pragma unroll
    for (int mi = 0; mi < 4; mi++)
#pragma unroll
        for (int ni = 0; ni < 8; ni++)
#pragma unroll
            for (int r = 0; r < 4; r++) acc[mi][ni][r] = 0.0f;

    gemm_main(g_Hh + (size_t)blockIdx.y * KT2 * A_TILE,
              g_w2h + (size_t)blockIdx.x * KT2 * B_TILE,
              KT2, sb, mb0, mb1, acc, tid, arow, axr, brow, bxr, abit, cbit);

    // epilogue: bias + output mask, scatter back to token order
#pragma unroll
    for (int mi = 0; mi < 4; mi++) {
        const int r = wm * 64 + mi * 16 + (lane >> 2);
#pragma unroll
        for (int hh = 0; hh < 2; hh++) {
            const int grow = row0 + r + hh * 8;
            const int tok  = g_perm[grow];
            const int d    = g_rowd[grow];
            float* op = out + (size_t)tok * DIM;
#pragma unroll
            for (int ni = 0; ni < 8; ni++) {
                const int col = n0 + wn * 64 + ni * 8 + 2 * (lane & 3);
                float2 rr;
                if (col < d) {   // d multiple of 128, col even -> pair uniform
                    const float2 bb = *(const float2*)(b2 + col);
                    rr = make_float2(acc[mi][ni][hh * 2 + 0] + bb.x,
                                     acc[mi][ni][hh * 2 + 1] + bb.y);
                } else {
                    rr = make_float2(0.f, 0.f);
                }
                *(float2*)(op + col) = rr;
            }
        }
    }
}

// ---------------- launch ----------------
extern "C" void kernel_launch(void* const* d_in, const int* in_sizes, int n_in,
                              void* d_out, int out_size) {
    const float* x    = (const float*)d_in[0];
    const float* w1   = (const float*)d_in[1];
    const float* b1   = (const float*)d_in[2];
    const float* w2   = (const float*)d_in[3];
    const float* b2   = (const float*)d_in[4];
    const int*   mask = (const int*)d_in[5];
    float* out = (float*)d_out;

    cudaFuncSetAttribute(k_gemm1, cudaFuncAttributeMaxDynamicSharedMemorySize, SMEM_BYTES);
    cudaFuncSetAttribute(k_gemm2, cudaFuncAttributeMaxDynamicSharedMemorySize, SMEM_BYTES);

    k_hist<<<1, 1024>>>(mask);                              // launch 0
    k_scatter_prep<<<T_TOK / TPB_TOKENS, 256>>>(x, mask);   // launch 1
    k_cvt<<<(4 * HID * DIM / 16) / 256, 256>>>(w1, w2);     // launch 2 (1M chunks)

    dim3 g1(HID / BN, T_TOK / BM);
    k_gemm1<<<g1, NT, SMEM_BYTES>>>(b1);                    // launch 3

    dim3 g2(DIM / BN, T_TOK / BM);
    k_gemm2<<<g2, NT, SMEM_BYTES>>>(b2, out);               // launch 4
}

// round 13
// speedup vs baseline: 1.0467x; 1.0467x over previous
#include <cuda_runtime.h>
#include <cuda_fp16.h>
#include <cstdint>

#define T_TOK 16384
#define DIM   1024
#define HID   4096

#define BM 128
#define BN 256
#define BK 64                       // 64 halves = 128B of K per row
#define NT 256                      // 8 warps: 2x4 grid, warp tile 64x64
#define KT1 (DIM / BK)              // 16 k-tiles (gemm1)
#define KT2 (HID / BK)              // 64 k-tiles (gemm2)
#define NROWT (T_TOK / BM)          // 128 row tiles

#define A_TILE 16384                // 128 rows x 128B
#define B_TILE 32768                // 256 rows x 128B
#define PAIR_A (2 * A_TILE)         // 32768
#define PAIR_B (2 * B_TILE)         // 65536
#define PAIR_BYTES (PAIR_A + PAIR_B)   // 98304
#define SMEM_BYTES (2 * PAIR_BYTES)    // 196608

#define G1_BLOCKS (NROWT * KT1)        // 2048 (16 col tiles per row)
#define G2_BLOCKS (NROWT * (DIM / BN)) // 512
#define ROWP 1040                      // gemm2 stage row stride (bytes)

// ---------------- scratch: pre-swizzled tiled fp16 operands ----------------
__device__ __align__(256) unsigned char g_Xh[(size_t)T_TOK * DIM * 2];   // 32MB
__device__ __align__(256) unsigned char g_Hh[(size_t)T_TOK * HID * 2];   // 128MB
__device__ __align__(256) unsigned char g_w1h[(size_t)HID * DIM * 2];    // 8MB
__device__ __align__(256) unsigned char g_w2h[(size_t)DIM * HID * 2];    // 8MB
__device__ int g_perm[T_TOK];
__device__ int g_rowd[T_TOK];
__device__ int g_off[4], g_cur[4];
__device__ int g_flag[NROWT];       // gemm1 col-tiles completed per row tile

// ---------------- helpers ----------------
__device__ __forceinline__ uint32_t smem_u32(const void* p) {
    return (uint32_t)__cvta_generic_to_shared(p);
}
__device__ __forceinline__ uint32_t swz(uint32_t r, uint32_t c8) {
    return r * 128u + (((c8) ^ (r & 7u)) << 4);
}
__device__ __forceinline__ float gelu_exact(float v) {
    return 0.5f * v * (1.0f + erff(v * 0.70710678118654752f));
}
__device__ __forceinline__ int ld_acquire(const int* p) {
    int v;
    asm volatile("ld.acquire.gpu.global.s32 %0, [%1];" : "=r"(v) : "l"(p) : "memory");
    return v;
}

#define MBAR_INIT(a, n) \
    asm volatile("mbarrier.init.shared.b64 [%0], %1;" :: "r"(a), "r"((uint32_t)(n)) : "memory")
#define MBAR_EXPECT_TX(a, b) \
    asm volatile("mbarrier.arrive.expect_tx.shared.b64 _, [%0], %1;" :: "r"(a), "r"((uint32_t)(b)) : "memory")
#define MBAR_WAIT(a, par) do {                                              \
    asm volatile("{\n\t.reg .pred P1;\n\t"                                  \
        "WL_%=:\n\t"                                                        \
        "mbarrier.try_wait.parity.acquire.cta.shared::cta.b64 P1, [%0], %1, 0x989680;\n\t" \
        "@P1 bra.uni WD_%=;\n\t"                                            \
        "bra.uni WL_%=;\n\t"                                                \
        "WD_%=:\n\t}"                                                       \
        :: "r"(a), "r"((uint32_t)(par)) : "memory");                        \
} while (0)
#define BULK_G2S(dst, src, nbytes, mbar) \
    asm volatile("cp.async.bulk.shared::cluster.global.mbarrier::complete_tx::bytes [%0], [%1], %2, [%3];" \
        :: "r"(dst), "l"(src), "r"((uint32_t)(nbytes)), "r"(mbar) : "memory")

#define LDSM_X4(r0, r1, r2, r3, addr) \
    asm volatile("ldmatrix.sync.aligned.m8n8.x4.shared.b16 {%0,%1,%2,%3}, [%4];" \
        : "=r"(r0), "=r"(r1), "=r"(r2), "=r"(r3) : "r"(addr))

__device__ __forceinline__ void mma16(float* c, const uint32_t* a, uint32_t b0, uint32_t b1) {
    asm volatile(
        "mma.sync.aligned.m16n8k16.row.col.f32.f16.f16.f32 "
        "{%0,%1,%2,%3}, {%4,%5,%6,%7}, {%8,%9}, {%0,%1,%2,%3};\n"
        : "+f"(c[0]), "+f"(c[1]), "+f"(c[2]), "+f"(c[3])
        : "r"(a[0]), "r"(a[1]), "r"(a[2]), "r"(a[3]), "r"(b0), "r"(b1));
}

// ---------------- launch 0: histogram + offsets + zero flags (one CTA) ----------------
__global__ void k_hist(const int* __restrict__ mask) {
    const int tid = threadIdx.x;          // 1024 threads
    if (tid < NROWT) g_flag[tid] = 0;
    int c0 = 0, c1 = 0, c2 = 0, c3 = 0;
    const int4* m4 = (const int4*)mask;
    for (int i = tid; i < T_TOK / 4; i += 1024) {
        const int4 e = m4[i];
        c0 += (e.x == 0) + (e.y == 0) + (e.z == 0) + (e.w == 0);
        c1 += (e.x == 1) + (e.y == 1) + (e.z == 1) + (e.w == 1);
        c2 += (e.x == 2) + (e.y == 2) + (e.z == 2) + (e.w == 2);
        c3 += (e.x == 3) + (e.y == 3) + (e.z == 3) + (e.w == 3);
    }
#pragma unroll
    for (int o = 16; o; o >>= 1) {
        c0 += __shfl_xor_sync(~0u, c0, o);
        c1 += __shfl_xor_sync(~0u, c1, o);
        c2 += __shfl_xor_sync(~0u, c2, o);
        c3 += __shfl_xor_sync(~0u, c3, o);
    }
    __shared__ int sh[4];
    if (tid < 4) sh[tid] = 0;
    __syncthreads();
    if ((tid & 31) == 0) {
        atomicAdd(&sh[0], c0); atomicAdd(&sh[1], c1);
        atomicAdd(&sh[2], c2); atomicAdd(&sh[3], c3);
    }
    __syncthreads();
    if (tid == 0) {
        int s = 0;
        for (int e = 0; e < 4; e++) { g_off[e] = s; s += sh[e]; g_cur[e] = 0; }
    }
}

// ---------------- launch 1: fused prep (scatter+x-convert | weight-convert) ----------------
#define TPB_TOKENS 64
__global__ void k_prep(const float* __restrict__ x, const int* __restrict__ mask,
                       const float* __restrict__ w1, const float* __restrict__ w2) {
    const int tid = threadIdx.x;          // 256 threads
    if (blockIdx.x < 256) {
        // ---- scatter rank + gather + K-mask + fp16 + tile/swizzle of x ----
        __shared__ int sp[TPB_TOKENS], sd[TPB_TOKENS];
        const int base = blockIdx.x * TPB_TOKENS;
        if (tid < TPB_TOKENS) {
            const int t = base + tid;
            const int e = mask[t];
            const int p = g_off[e] + atomicAdd(&g_cur[e], 1);
            g_perm[p] = t;
            g_rowd[p] = 128 << e;
            sp[tid] = p;
            sd[tid] = 128 << e;
        }
        __syncthreads();
        const int sub = tid >> 7;             // 0..1
        const int cc  = tid & 127;            // 16B-chunk index in 2KB row
        const int tkt = cc >> 3;              // k-tile 0..15
        const int c8  = cc & 7;
        for (int tk = 0; tk < TPB_TOKENS; tk += 2) {
            const int tok = base + tk + sub;
            const int p = sp[tk + sub], d = sd[tk + sub];
            const int i = p >> 7, r = p & 127;
            uint4 v = make_uint4(0u, 0u, 0u, 0u);
            if (cc * 8 < d) {
                const float4 f0 = ((const float4*)(x + (size_t)tok * DIM + cc * 8))[0];
                const float4 f1 = ((const float4*)(x + (size_t)tok * DIM + cc * 8))[1];
                __half2 h0 = __floats2half2_rn(f0.x, f0.y);
                __half2 h1 = __floats2half2_rn(f0.z, f0.w);
                __half2 h2 = __floats2half2_rn(f1.x, f1.y);
                __half2 h3 = __floats2half2_rn(f1.z, f1.w);
                v.x = *(uint32_t*)&h0; v.y = *(uint32_t*)&h1;
                v.z = *(uint32_t*)&h2; v.w = *(uint32_t*)&h3;
            }
            *(uint4*)(g_Xh + (size_t)(i * KT1 + tkt) * A_TILE + swz(r, c8)) = v;
        }
    } else {
        // ---- weight conversion + tile/swizzle ----
        const int q = (blockIdx.x - 256) * 256 + tid;      // one 16B chunk
        const int n1 = (HID * DIM * 2) / 16;               // 524288 chunks (w1)
        const float* src;
        unsigned char* dst;
        if (q < n1) {
            const int tile = q >> 11;
            const int w = q & 2047;
            const int r = w >> 3, c8 = w & 7;
            const int j = tile >> 4, t = tile & (KT1 - 1);
            src = w1 + (size_t)(j * 256 + r) * DIM + t * 64 + c8 * 8;
            dst = g_w1h + (size_t)tile * B_TILE + swz(r, c8);
        } else {
            const int p = q - n1;
            const int tile = p >> 11;
            const int w = p & 2047;
            const int r = w >> 3, c8 = w & 7;
            const int j = tile >> 6, t = tile & (KT2 - 1);
            src = w2 + (size_t)(j * 256 + r) * HID + t * 64 + c8 * 8;
            dst = g_w2h + (size_t)tile * B_TILE + swz(r, c8);
        }
        const float4 f0 = ((const float4*)src)[0];
        const float4 f1 = ((const float4*)src)[1];
        __half2 h0 = __floats2half2_rn(f0.x, f0.y);
        __half2 h1 = __floats2half2_rn(f0.z, f0.w);
        __half2 h2 = __floats2half2_rn(f1.x, f1.y);
        __half2 h3 = __floats2half2_rn(f1.z, f1.w);
        uint4 v;
        v.x = *(uint32_t*)&h0; v.y = *(uint32_t*)&h1;
        v.z = *(uint32_t*)&h2; v.w = *(uint32_t*)&h3;
        *(uint4*)dst = v;
    }
}

// ---------------- per-stage compute: warp tile 64x64, xor-swizzled LDSM ----------------
__device__ __forceinline__ void tile_compute(uint32_t sA, uint32_t sB,
                                             const uint32_t (&arow)[4], const uint32_t (&axr)[4],
                                             const uint32_t (&brow)[4], const uint32_t (&bxr)[4],
                                             uint32_t abit, uint32_t cbit,
                                             float (&acc)[4][8][4]) {
#pragma unroll
    for (uint32_t kc = 0; kc < 4; kc++) {
        uint32_t a[4][4], b[4][4];
        const uint32_t ca = kc * 2 + cbit;
        const uint32_t cb = kc * 2 + abit;
#pragma unroll
        for (int mi = 0; mi < 4; mi++) {
            LDSM_X4(a[mi][0], a[mi][1], a[mi][2], a[mi][3],
                    sA + arow[mi] + ((ca ^ axr[mi]) << 4));
        }
#pragma unroll
        for (int g = 0; g < 4; g++) {
            LDSM_X4(b[g][0], b[g][1], b[g][2], b[g][3],
                    sB + brow[g] + ((cb ^ bxr[g]) << 4));
        }
#pragma unroll
        for (int mi = 0; mi < 4; mi++)
#pragma unroll
            for (int g = 0; g < 4; g++) {
                mma16(acc[mi][2 * g],     a[mi], b[g][0], b[g][1]);
                mma16(acc[mi][2 * g + 1], a[mi], b[g][2], b[g][3]);
            }
    }
}

// ---------------- GEMM mainloop: bulk-copy pairs, 2 buffers, 2 mbarriers ----------------
__device__ __forceinline__ void gemm_main(const unsigned char* __restrict__ At,
                                          const unsigned char* __restrict__ Bt,
                                          int nk, uint32_t sb, uint32_t mb0, uint32_t mb1,
                                          float (&acc)[4][8][4], int tid,
                                          const uint32_t (&arow)[4], const uint32_t (&axr)[4],
                                          const uint32_t (&brow)[4], const uint32_t (&bxr)[4],
                                          uint32_t abit, uint32_t cbit) {
    const int npair = nk >> 1;               // nk even: {2,4,8,16,64}
    if (tid == 0) {
        MBAR_EXPECT_TX(mb0, PAIR_BYTES);
        BULK_G2S(sb, At, PAIR_A, mb0);
        BULK_G2S(sb + PAIR_A, Bt, PAIR_B, mb0);
        if (npair > 1) {
            MBAR_EXPECT_TX(mb1, PAIR_BYTES);
            BULK_G2S(sb + PAIR_BYTES, At + PAIR_A, PAIR_A, mb1);
            BULK_G2S(sb + PAIR_BYTES + PAIR_A, Bt + PAIR_B, PAIR_B, mb1);
        }
    }
    for (int ip = 0; ip < npair; ip++) {
        MBAR_WAIT((ip & 1) ? mb1 : mb0, (ip >> 1) & 1);
        const uint32_t st = sb + (ip & 1) * PAIR_BYTES;
        tile_compute(st, st + PAIR_A, arow, axr, brow, bxr, abit, cbit, acc);
        tile_compute(st + A_TILE, st + PAIR_A + B_TILE, arow, axr, brow, bxr, abit, cbit, acc);
        __syncthreads();
        const int np = ip + 2;
        if (np < npair && tid == 0) {
            const uint32_t mb = (ip & 1) ? mb1 : mb0;
            MBAR_EXPECT_TX(mb, PAIR_BYTES);
            BULK_G2S(st, At + (size_t)np * PAIR_A, PAIR_A, mb);
            BULK_G2S(st + PAIR_A, Bt + (size_t)np * PAIR_B, PAIR_B, mb);
        }
    }
    __syncthreads();                          // last pair buffer free -> stage reuse OK
}

// ---------------- launch 2 — fused GEMM1+GEMM2 with row-tile flags ----------------
__global__ void __launch_bounds__(NT, 1)
k_gemm(const float* __restrict__ b1, const float* __restrict__ b2,
       float* __restrict__ out) {
    extern __shared__ __align__(1024) char smdyn[];
    __shared__ __align__(8) uint64_t s_mbar[2];
    __shared__ int s_tok[BM];
    const uint32_t sb  = smem_u32(smdyn);
    const uint32_t mb0 = smem_u32(&s_mbar[0]);
    const uint32_t mb1 = smem_u32(&s_mbar[1]);

    const int bid  = blockIdx.x;
    const int tid  = threadIdx.x;
    const int lane = tid & 31, wid = tid >> 5;
    const int wm = wid >> 2, wn = wid & 3;

    const uint32_t lr   = lane & 7;
    const uint32_t abit = (lane >> 3) & 1;
    const uint32_t cbit = (lane >> 4) & 1;
    uint32_t arow[4], axr[4], brow[4], bxr[4];
#pragma unroll
    for (int mi = 0; mi < 4; mi++) {
        const uint32_t r = wm * 64 + mi * 16 + lr + abit * 8;
        arow[mi] = r * 128u; axr[mi] = r & 7u;
    }
#pragma unroll
    for (int g = 0; g < 4; g++) {
        const uint32_t r = wn * 64 + g * 16 + lr + cbit * 8;
        brow[g] = r * 128u; bxr[g] = r & 7u;
    }

    if (bid < G1_BLOCKS) {
        // ================= GEMM1: H = gelu(Xh @ W1h^T + b1) =================
        const int ti = bid >> 4;            // row tile (row-major: early rows first)
        const int xc = bid & 15;            // column tile
        const int n0 = xc * BN;
        const int row0 = ti * BM;

        if (tid == 0) { MBAR_INIT(mb0, 1); MBAR_INIT(mb1, 1); }
        __syncthreads();

        float acc[4][8][4];
#pragma unroll
        for (int mi = 0; mi < 4; mi++)
#pragma unroll
            for (int ni = 0; ni < 8; ni++)
#pragma unroll
                for (int r = 0; r < 4; r++) acc[mi][ni][r] = 0.0f;

        const int nk = g_rowd[row0 + BM - 1] / BK;   // sorted: last row has max d

        gemm_main(g_Xh + (size_t)ti * KT1 * A_TILE,
                  g_w1h + (size_t)xc * KT1 * B_TILE,
                  nk, sb, mb0, mb1, acc, tid, arow, axr, brow, bxr, abit, cbit);

        // hoisted bias
        float2 bb[8];
#pragma unroll
        for (int ni = 0; ni < 8; ni++)
            bb[ni] = *(const float2*)(b1 + n0 + wn * 64 + ni * 8 + 2 * (lane & 3));

        // stage epilogue into smem in g_Hh tile layout (4 local k-tiles x 16KB)
#pragma unroll
        for (int mi = 0; mi < 4; mi++) {
            const int rA = wm * 64 + mi * 16 + (lane >> 2);
#pragma unroll
            for (int hh = 0; hh < 2; hh++) {
                const uint32_t r = (uint32_t)(rA + hh * 8);
#pragma unroll
                for (int ni = 0; ni < 8; ni++) {
                    float v0 = gelu_exact(acc[mi][ni][hh * 2 + 0] + bb[ni].x);
                    float v1 = gelu_exact(acc[mi][ni][hh * 2 + 1] + bb[ni].y);
                    __half2 hv = __floats2half2_rn(v0, v1);
                    const uint32_t off = (uint32_t)wn * 16384u + r * 128u
                                       + (((uint32_t)ni ^ (r & 7u)) << 4)
                                       + ((lane & 3u) << 2);
                    *(uint32_t*)(smdyn + off) = *(uint32_t*)&hv;
                }
            }
        }
        __syncthreads();
        // coalesced copy: 64KB contiguous into g_Hh tiles (ti*KT2 + n0/64 .. +3)
        {
            unsigned char* dstb = g_Hh + ((size_t)ti * KT2 + (n0 >> 6)) * A_TILE;
            const uint4* s4 = (const uint4*)smdyn;
            uint4* d4 = (uint4*)dstb;
#pragma unroll
            for (int i = 0; i < 16; i++) d4[tid + i * NT] = s4[tid + i * NT];
        }
        __syncthreads();
        if (tid == 0) {
            __threadfence();
            atomicAdd(&g_flag[ti], 1);
        }
    } else {
        // ================= GEMM2: Y = mask_out(H @ W2h^T + b2) =================
        const int b2i = bid - G1_BLOCKS;
        const int ti = b2i >> 2;            // row tile
        const int xc = b2i & 3;
        const int n0 = xc * BN;
        const int row0 = ti * BM;
        const int dmax = g_rowd[row0 + BM - 1];

        if (tid < BM) s_tok[tid] = g_perm[row0 + tid];
        __syncthreads();

        if (n0 >= dmax) {   // fully masked tile: write zeros, no dependency
            const int row = tid >> 1, half = tid & 1;
            float4* op = (float4*)(out + (size_t)s_tok[row] * DIM + n0 + half * 128);
            const float4 z = make_float4(0.f, 0.f, 0.f, 0.f);
#pragma unroll
            for (int j = 0; j < 32; j++) op[j] = z;
            return;
        }

        if (tid == 0) {
            MBAR_INIT(mb0, 1); MBAR_INIT(mb1, 1);
            while (ld_acquire(&g_flag[ti]) < KT1) __nanosleep(128);
        }
        __syncthreads();

        float acc[4][8][4];
#pragma unroll
        for (int mi = 0; mi < 4; mi++)
#pragma unroll
            for (int ni = 0; ni < 8; ni++)
#pragma unroll
                for (int r = 0; r < 4; r++) acc[mi][ni][r] = 0.0f;

        gemm_main(g_Hh + (size_t)ti * KT2 * A_TILE,
                  g_w2h + (size_t)xc * KT2 * B_TILE,
                  KT2, sb, mb0, mb1, acc, tid, arow, axr, brow, bxr, abit, cbit);

        // hoisted bias
        float2 bb[8];
#pragma unroll
        for (int ni = 0; ni < 8; ni++)
            bb[ni] = *(const float2*)(b2 + n0 + wn * 64 + ni * 8 + 2 * (lane & 3));

        // stage epilogue into smem rows (ROWP-byte stride), masked
#pragma unroll
        for (int mi = 0; mi < 4; mi++) {
            const int rA = wm * 64 + mi * 16 + (lane >> 2);
#pragma unroll
            for (int hh = 0; hh < 2; hh++) {
                const int r = rA + hh * 8;
                const int d = g_rowd[row0 + r];
#pragma unroll
                for (int ni = 0; ni < 8; ni++) {
                    const int col = n0 + wn * 64 + ni * 8 + 2 * (lane & 3);
                    float2 rr;
                    if (col < d) {
                        rr = make_float2(acc[mi][ni][hh * 2 + 0] + bb[ni].x,
                                         acc[mi][ni][hh * 2 + 1] + bb[ni].y);
                    } else {
                        rr = make_float2(0.f, 0.f);
                    }
                    *(float2*)(smdyn + r * ROWP + (col - n0) * 4) = rr;
                }
            }
        }
        __syncthreads();
        // coalesced copy: 128 rows x 1KB to scattered token rows
#pragma unroll
        for (int i = 0; i < 32; i++) {
            const int chunk = tid + i * NT;          // 8192 chunks
            const int r = chunk >> 6, c16 = chunk & 63;
            const uint4 v = *(const uint4*)(smdyn + r * ROWP + c16 * 16);
            ((uint4*)(out + (size_t)s_tok[r] * DIM + n0))[c16] = v;
        }
    }
}

// ---------------- launch ----------------
extern "C" void kernel_launch(void* const* d_in, const int* in_sizes, int n_in,
                              void* d_out, int out_size) {
    const float* x    = (const float*)d_in[0];
    const float* w1   = (const float*)d_in[1];
    const float* b1   = (const float*)d_in[2];
    const float* w2   = (const float*)d_in[3];
    const float* b2   = (const float*)d_in[4];
    const int*   mask = (const int*)d_in[5];
    float* out = (float*)d_out;

    cudaFuncSetAttribute(k_gemm, cudaFuncAttributeMaxDynamicSharedMemorySize, SMEM_BYTES);

    k_hist<<<1, 1024>>>(mask);                          // launch 0
    k_prep<<<256 + 4096, 256>>>(x, mask, w1, w2);       // launch 1 (fused prep)
    k_gemm<<<G1_BLOCKS + G2_BLOCKS, NT, SMEM_BYTES>>>(b1, b2, out);   // launch 2
}